// round 1
// baseline (speedup 1.0000x reference)
#include <cuda_runtime.h>
#include <math.h>

// Problem constants
#define D_IN      40
#define WID       128
#define NSEG      2048
#define NHEADS    4
#define MAXN      500000
#define TILE_ROWS 64
#define ENC_THREADS 512
#define H_STRIDE  132   // padded row stride for activation tile (bank-conflict free)

// ---------------------------------------------------------------------------
// Device scratch (static __device__ allocation is the sanctioned scratch path)
// ---------------------------------------------------------------------------
__device__ __align__(16) float g_segSum[NSEG * WID];       // 1 MB
__device__ float g_segCnt[NSEG];
__device__ __align__(16) float g_t[NSEG * NHEADS];         // per-segment logit term
__device__ __align__(16) float g_den[NSEG * NHEADS];       // softmax denominators
__device__ __align__(16) float g_V[(D_IN + WID) * NHEADS]; // folded W_k @ W_q  [168][4]
__device__ __align__(16) float g_P[MAXN * NHEADS];         // exp(logits) scratch

// ---------------------------------------------------------------------------
// K0: zero accumulators
// ---------------------------------------------------------------------------
__global__ void k_zero() {
    int i = blockIdx.x * blockDim.x + threadIdx.x;
    int stride = gridDim.x * blockDim.x;
    for (int j = i; j < NSEG * WID; j += stride) g_segSum[j] = 0.f;
    for (int j = i; j < NSEG; j += stride) g_segCnt[j] = 0.f;
    for (int j = i; j < NSEG * NHEADS; j += stride) g_den[j] = 0.f;
}

// ---------------------------------------------------------------------------
// K1: fold V[d][h] = sum_k W_k[d, h*64+k] * W_q[h,k]
// ---------------------------------------------------------------------------
__global__ void k_fold(const float* __restrict__ Wk, const float* __restrict__ Wq) {
    int i = threadIdx.x;
    if (i < (D_IN + WID) * NHEADS) {
        int d = i >> 2, h = i & 3;
        float s = 0.f;
        const float* wk = Wk + d * 256 + h * 64;
        const float* wq = Wq + h * 64;
#pragma unroll 8
        for (int k = 0; k < 64; k++) s += wk[k] * wq[k];
        g_V[i] = s;
    }
}

// ---------------------------------------------------------------------------
// K2: fused encoder MLP (40->128->128->128, relu) + sorted-segment accumulation
// Persistent blocks; all weights in SMEM; single activation tile, reg-staged.
// Thread tile: 2 rows x 8 cols.  512 threads cover 64x128 output.
// ---------------------------------------------------------------------------
template <int K, int ASTR>
__device__ __forceinline__ void layer_compute(const float* __restrict__ A,
                                              const float* __restrict__ W,
                                              int rg, int cg, float* acc) {
#pragma unroll
    for (int j = 0; j < 16; j++) acc[j] = 0.f;
    const float* a0 = A + (2 * rg) * ASTR;
    const float* wp = W + cg * 8;
#pragma unroll 4
    for (int k = 0; k < K; k++) {
        float x0 = a0[k];
        float x1 = a0[k + ASTR];
        float4 wa = *reinterpret_cast<const float4*>(wp + k * 128);
        float4 wb = *reinterpret_cast<const float4*>(wp + k * 128 + 4);
        acc[0]  += x0 * wa.x; acc[1]  += x0 * wa.y; acc[2]  += x0 * wa.z; acc[3]  += x0 * wa.w;
        acc[4]  += x0 * wb.x; acc[5]  += x0 * wb.y; acc[6]  += x0 * wb.z; acc[7]  += x0 * wb.w;
        acc[8]  += x1 * wa.x; acc[9]  += x1 * wa.y; acc[10] += x1 * wa.z; acc[11] += x1 * wa.w;
        acc[12] += x1 * wb.x; acc[13] += x1 * wb.y; acc[14] += x1 * wb.z; acc[15] += x1 * wb.w;
    }
}

__device__ __forceinline__ void store_relu(float* __restrict__ H, const float* __restrict__ bias,
                                           int rg, int cg, const float* acc) {
    float4 ba = *reinterpret_cast<const float4*>(bias + cg * 8);
    float4 bb = *reinterpret_cast<const float4*>(bias + cg * 8 + 4);
    float* p = H + (2 * rg) * H_STRIDE + cg * 8;
    float4 o;
    o.x = fmaxf(acc[0] + ba.x, 0.f); o.y = fmaxf(acc[1] + ba.y, 0.f);
    o.z = fmaxf(acc[2] + ba.z, 0.f); o.w = fmaxf(acc[3] + ba.w, 0.f);
    *reinterpret_cast<float4*>(p) = o;
    o.x = fmaxf(acc[4] + bb.x, 0.f); o.y = fmaxf(acc[5] + bb.y, 0.f);
    o.z = fmaxf(acc[6] + bb.z, 0.f); o.w = fmaxf(acc[7] + bb.w, 0.f);
    *reinterpret_cast<float4*>(p + 4) = o;
    p += H_STRIDE;
    o.x = fmaxf(acc[8]  + ba.x, 0.f); o.y = fmaxf(acc[9]  + ba.y, 0.f);
    o.z = fmaxf(acc[10] + ba.z, 0.f); o.w = fmaxf(acc[11] + ba.w, 0.f);
    *reinterpret_cast<float4*>(p) = o;
    o.x = fmaxf(acc[12] + bb.x, 0.f); o.y = fmaxf(acc[13] + bb.y, 0.f);
    o.z = fmaxf(acc[14] + bb.z, 0.f); o.w = fmaxf(acc[15] + bb.w, 0.f);
    *reinterpret_cast<float4*>(p + 4) = o;
}

// SMEM layout (floats):
//   sW1: 0      (40*128 = 5120)
//   sB1: 5120   (128)   sB2: 5248   sB3: 5376
//   sW2: 5504   (16384)
//   sW3: 21888  (16384)
//   sX : 38272  (64*40 = 2560)
//   sH : 40832  (64*132 = 8448)
//   sSeg: 49280 (64 ints)
#define ENC_SMEM_FLOATS 49280
#define ENC_SMEM_BYTES  (ENC_SMEM_FLOATS * 4 + TILE_ROWS * 4)

__global__ void __launch_bounds__(ENC_THREADS, 1)
k_encoder(const float* __restrict__ X, const int* __restrict__ seg,
          const float* __restrict__ W1, const float* __restrict__ b1,
          const float* __restrict__ W2, const float* __restrict__ b2,
          const float* __restrict__ W3, const float* __restrict__ b3,
          int N, int numTiles) {
    extern __shared__ float sm[];
    float* sW1 = sm;
    float* sB1 = sm + 5120;
    float* sB2 = sm + 5248;
    float* sB3 = sm + 5376;
    float* sW2 = sm + 5504;
    float* sW3 = sm + 21888;
    float* sX  = sm + 38272;
    float* sH  = sm + 40832;
    int*   sSeg = (int*)(sm + ENC_SMEM_FLOATS);

    int tid = threadIdx.x;
    int cg = tid & 15;   // col group: 8 cols each
    int rg = tid >> 4;   // row group: 2 rows each

    // Load weights once per block
    for (int i = tid; i < 5120; i += ENC_THREADS) sW1[i] = W1[i];
    for (int i = tid; i < 128; i += ENC_THREADS) { sB1[i] = b1[i]; sB2[i] = b2[i]; sB3[i] = b3[i]; }
    for (int i = tid; i < 16384; i += ENC_THREADS) { sW2[i] = W2[i]; sW3[i] = W3[i]; }

    float acc[16];

    for (int tile = blockIdx.x; tile < numTiles; tile += gridDim.x) {
        int row0 = tile * TILE_ROWS;
        int valid = N - row0; if (valid > TILE_ROWS) valid = TILE_ROWS;

        __syncthreads();  // protect sX/sSeg/sH vs previous tile's readers

        for (int i = tid; i < TILE_ROWS * D_IN; i += ENC_THREADS) {
            int g = row0 * D_IN + i;
            sX[i] = (g < N * D_IN) ? X[g] : 0.f;
        }
        if (tid < TILE_ROWS) sSeg[tid] = (row0 + tid < N) ? seg[row0 + tid] : -1;
        __syncthreads();

        // layer 1: sX -> sH
        layer_compute<D_IN, D_IN>(sX, sW1, rg, cg, acc);
        store_relu(sH, sB1, rg, cg, acc);
        __syncthreads();
        // layer 2: sH -> regs -> sH
        layer_compute<WID, H_STRIDE>(sH, sW2, rg, cg, acc);
        __syncthreads();
        store_relu(sH, sB2, rg, cg, acc);
        __syncthreads();
        // layer 3: sH -> regs -> sH (enc)
        layer_compute<WID, H_STRIDE>(sH, sW3, rg, cg, acc);
        __syncthreads();
        store_relu(sH, sB3, rg, cg, acc);
        __syncthreads();

        // Sorted-segment accumulation: thread c owns column c; thread 128 owns counts.
        if (tid < WID) {
            int c = tid;
            float a = 0.f; int cur = sSeg[0];
            for (int r = 0; r < valid; r++) {
                int s = sSeg[r];
                if (s != cur) { atomicAdd(&g_segSum[cur * WID + c], a); a = 0.f; cur = s; }
                a += sH[r * H_STRIDE + c];
            }
            if (valid > 0) atomicAdd(&g_segSum[cur * WID + c], a);
        } else if (tid == WID) {
            float a = 0.f; int cur = sSeg[0];
            for (int r = 0; r < valid; r++) {
                int s = sSeg[r];
                if (s != cur) { atomicAdd(&g_segCnt[cur], a); a = 0.f; cur = s; }
                a += 1.f;
            }
            if (valid > 0) atomicAdd(&g_segCnt[cur], a);
        }
    }
}

// ---------------------------------------------------------------------------
// K3: rho — agg = relu(mean @ Wr + br); then fold to t[s,h] = agg . V[40:,h]
// One block per segment, 128 threads.
// ---------------------------------------------------------------------------
__global__ void k_rho(const float* __restrict__ Wr, const float* __restrict__ br) {
    __shared__ float mean[WID];
    __shared__ float part[4 * NHEADS];
    int s = blockIdx.x;
    int c = threadIdx.x;
    float cnt = g_segCnt[s];
    float inv = 1.f / fmaxf(cnt, 1.f);
    mean[c] = g_segSum[s * WID + c] * inv;
    __syncthreads();

    float acc = br[c];
#pragma unroll 8
    for (int k = 0; k < WID; k++) acc += mean[k] * Wr[k * WID + c];
    float a = fmaxf(acc, 0.f);

    float p0 = a * g_V[(D_IN + c) * 4 + 0];
    float p1 = a * g_V[(D_IN + c) * 4 + 1];
    float p2 = a * g_V[(D_IN + c) * 4 + 2];
    float p3 = a * g_V[(D_IN + c) * 4 + 3];
#pragma unroll
    for (int off = 16; off > 0; off >>= 1) {
        p0 += __shfl_down_sync(0xffffffffu, p0, off);
        p1 += __shfl_down_sync(0xffffffffu, p1, off);
        p2 += __shfl_down_sync(0xffffffffu, p2, off);
        p3 += __shfl_down_sync(0xffffffffu, p3, off);
    }
    int warp = c >> 5, lane = c & 31;
    if (lane == 0) {
        part[warp * 4 + 0] = p0; part[warp * 4 + 1] = p1;
        part[warp * 4 + 2] = p2; part[warp * 4 + 3] = p3;
    }
    __syncthreads();
    if (c < NHEADS) {
        g_t[s * 4 + c] = part[0 * 4 + c] + part[1 * 4 + c] + part[2 * 4 + c] + part[3 * 4 + c];
    }
}

// ---------------------------------------------------------------------------
// K4: per-row logits + exp + segment denominator (warp-aggregated atomics)
// ---------------------------------------------------------------------------
__global__ void k_attn(const float* __restrict__ X, const int* __restrict__ seg, int N) {
    __shared__ float sX[256 * 41];
    __shared__ float sV[D_IN * NHEADS];
    int tid = threadIdx.x;
    int base = blockIdx.x * 256;

    if (tid < D_IN * NHEADS) sV[tid] = g_V[tid];
    for (int i = tid; i < 256 * D_IN; i += 256) {
        int g = base * D_IN + i;
        int r = i / D_IN, d = i - r * D_IN;
        sX[r * 41 + d] = (g < N * D_IN) ? X[g] : 0.f;
    }
    __syncthreads();

    int n = base + tid;
    bool ok = (n < N);
    int sg = ok ? seg[n] : -1;
    int sgl = (sg >= 0) ? sg : 0;

    float p0 = 0.f, p1 = 0.f, p2 = 0.f, p3 = 0.f;
    const float* xr = sX + tid * 41;
#pragma unroll
    for (int d = 0; d < D_IN; d++) {
        float x = xr[d];
        p0 += x * sV[d * 4 + 0]; p1 += x * sV[d * 4 + 1];
        p2 += x * sV[d * 4 + 2]; p3 += x * sV[d * 4 + 3];
    }
    const float sc = 0.125f;  // 1/sqrt(64)
    float e0 = ok ? __expf((p0 + g_t[sgl * 4 + 0]) * sc) : 0.f;
    float e1 = ok ? __expf((p1 + g_t[sgl * 4 + 1]) * sc) : 0.f;
    float e2 = ok ? __expf((p2 + g_t[sgl * 4 + 2]) * sc) : 0.f;
    float e3 = ok ? __expf((p3 + g_t[sgl * 4 + 3]) * sc) : 0.f;

    if (ok) {
        float4 e = make_float4(e0, e1, e2, e3);
        *reinterpret_cast<float4*>(&g_P[n * 4]) = e;
    }

    // warp-aggregated denominator atomics (rows are segment-sorted)
    unsigned full = 0xffffffffu;
    int lane = tid & 31;
    int sg0 = __shfl_sync(full, sg, 0);
    bool uni = __all_sync(full, sg == sg0);
    if (uni) {
        float r0 = e0, r1 = e1, r2 = e2, r3 = e3;
#pragma unroll
        for (int off = 16; off > 0; off >>= 1) {
            r0 += __shfl_down_sync(full, r0, off);
            r1 += __shfl_down_sync(full, r1, off);
            r2 += __shfl_down_sync(full, r2, off);
            r3 += __shfl_down_sync(full, r3, off);
        }
        if (lane == 0 && sg0 >= 0) {
            atomicAdd(&g_den[sg0 * 4 + 0], r0); atomicAdd(&g_den[sg0 * 4 + 1], r1);
            atomicAdd(&g_den[sg0 * 4 + 2], r2); atomicAdd(&g_den[sg0 * 4 + 3], r3);
        }
    } else if (sg >= 0) {
        atomicAdd(&g_den[sg * 4 + 0], e0); atomicAdd(&g_den[sg * 4 + 1], e1);
        atomicAdd(&g_den[sg * 4 + 2], e2); atomicAdd(&g_den[sg * 4 + 3], e3);
    }
}

// ---------------------------------------------------------------------------
// K5: normalize and write output [HEADS, N, 1]
// ---------------------------------------------------------------------------
__global__ void k_norm(const int* __restrict__ seg, float* __restrict__ out, int N) {
    int n = blockIdx.x * 256 + threadIdx.x;
    if (n >= N) return;
    float4 e = *reinterpret_cast<const float4*>(&g_P[n * 4]);
    int s = seg[n];
    float4 d = *reinterpret_cast<const float4*>(&g_den[s * 4]);
    out[0 * N + n] = e.x / d.x;
    out[1 * N + n] = e.y / d.y;
    out[2 * N + n] = e.z / d.z;
    out[3 * N + n] = e.w / d.w;
}

// ---------------------------------------------------------------------------
extern "C" void kernel_launch(void* const* d_in, const int* in_sizes, int n_in,
                              void* d_out, int out_size) {
    const float* X  = (const float*)d_in[0];
    const int*   sg = (const int*)d_in[1];
    // d_in[2] = lengths (unused by the reference computation)
    const float* W1 = (const float*)d_in[3];
    const float* b1 = (const float*)d_in[4];
    const float* W2 = (const float*)d_in[5];
    const float* b2 = (const float*)d_in[6];
    const float* W3 = (const float*)d_in[7];
    const float* b3 = (const float*)d_in[8];
    const float* Wr = (const float*)d_in[9];
    const float* br = (const float*)d_in[10];
    const float* Wk = (const float*)d_in[11];
    const float* Wq = (const float*)d_in[12];
    float* out = (float*)d_out;

    int N = in_sizes[0] / D_IN;
    int tiles = (N + TILE_ROWS - 1) / TILE_ROWS;

    cudaFuncSetAttribute(k_encoder, cudaFuncAttributeMaxDynamicSharedMemorySize, ENC_SMEM_BYTES);

    k_zero<<<64, 256>>>();
    k_fold<<<1, (D_IN + WID) * NHEADS>>>(Wk, Wq);
    k_encoder<<<152, ENC_THREADS, ENC_SMEM_BYTES>>>(X, sg, W1, b1, W2, b2, W3, b3, N, tiles);
    k_rho<<<NSEG, WID>>>(Wr, br);
    k_attn<<<(N + 255) / 256, 256>>>(X, sg, N);
    k_norm<<<(N + 255) / 256, 256>>>(sg, out, N);
}

// round 2
// speedup vs baseline: 2.4360x; 2.4360x over previous
#include <cuda_runtime.h>
#include <math.h>

// Problem constants
#define D_IN      40
#define WID       128
#define NSEG      2048
#define NHEADS    4
#define MAXN      500000
#define TILE      128           // rows per tile
#define ENC_T     512
#define HSTR      132           // padded row stride (floats) for transposed act tile

typedef unsigned long long ull;

// ---------------------------------------------------------------------------
// Device scratch
// ---------------------------------------------------------------------------
__device__ __align__(16) float g_segSum[NSEG * WID];
__device__ float g_segCnt[NSEG];
__device__ __align__(16) float g_t[NSEG * NHEADS];
__device__ __align__(16) float g_den[NSEG * NHEADS];
__device__ __align__(16) float g_V[(D_IN + WID) * NHEADS];  // folded W_k@W_q [168][4]
__device__ __align__(16) float g_P[MAXN * NHEADS];          // logit partials -> exp

// ---------------------------------------------------------------------------
// f32x2 helpers (packed dual-fp32 FMA, sm_100+)
// ---------------------------------------------------------------------------
__device__ __forceinline__ ull ffma2(ull a, ull b, ull c) {
    ull d;
    asm("fma.rn.f32x2 %0, %1, %2, %3;" : "=l"(d) : "l"(a), "l"(b), "l"(c));
    return d;
}
__device__ __forceinline__ ull pack2(float x) {
    ull d;
    asm("mov.b64 %0, {%1, %1};" : "=l"(d) : "f"(x));
    return d;
}
__device__ __forceinline__ void unpack2(ull v, float& lo, float& hi) {
    asm("mov.b64 {%0, %1}, %2;" : "=f"(lo), "=f"(hi) : "l"(v));
}

// ---------------------------------------------------------------------------
// K0: zero accumulators
// ---------------------------------------------------------------------------
__global__ void k_zero() {
    int i = blockIdx.x * blockDim.x + threadIdx.x;
    int stride = gridDim.x * blockDim.x;
    for (int j = i; j < NSEG * WID; j += stride) g_segSum[j] = 0.f;
    for (int j = i; j < NSEG; j += stride) g_segCnt[j] = 0.f;
    for (int j = i; j < NSEG * NHEADS; j += stride) g_den[j] = 0.f;
}

// ---------------------------------------------------------------------------
// K1: fold V[d][h] = sum_k W_k[d, h*64+k] * W_q[h,k]
// ---------------------------------------------------------------------------
__global__ void k_fold(const float* __restrict__ Wk, const float* __restrict__ Wq) {
    int i = threadIdx.x;
    if (i < (D_IN + WID) * NHEADS) {
        int d = i >> 2, h = i & 3;
        float s = 0.f;
        const float* wk = Wk + d * 256 + h * 64;
        const float* wq = Wq + h * 64;
#pragma unroll 8
        for (int k = 0; k < 64; k++) s += wk[k] * wq[k];
        g_V[i] = s;
    }
}

// ---------------------------------------------------------------------------
// K2: fused encoder. Transposed activations Ht[c][r] (stride HSTR), warp owns
// 8 columns (broadcast weight loads), lane owns 4 rows (one LDS.128 of acts),
// f32x2 packed FMA accumulators. In-place layers via register staging.
// Also emits per-row X.V[0:40] partial logits into g_P.
// ---------------------------------------------------------------------------
// SMEM float layout:
//  sV   : 0      (160)
//  sW1  : 160    (5120)
//  sB1  : 5280   (128)   sB2: 5408   sB3: 5536
//  sW2  : 5664   (16384)
//  sW3  : 22048  (16384)
//  sH   : 38432  (128*HSTR = 16896)   [Xt aliases the front 40*HSTR]
//  sSeg : 55328  (128 ints)
#define ENC_SMEM_FLOATS 55456
#define ENC_SMEM_BYTES  (ENC_SMEM_FLOATS * 4)

template <int K>
__device__ __forceinline__ void layerT(const float* __restrict__ At,
                                       const float* __restrict__ W,
                                       int c0, int r0, ull acc[4][4]) {
#pragma unroll
    for (int r = 0; r < 4; r++)
#pragma unroll
        for (int j = 0; j < 4; j++) acc[r][j] = 0ULL;
#pragma unroll 2
    for (int k = 0; k < K; k++) {
        float4 xv = *reinterpret_cast<const float4*>(At + k * HSTR + r0);
        ull x0 = pack2(xv.x), x1 = pack2(xv.y), x2 = pack2(xv.z), x3 = pack2(xv.w);
        ulonglong2 wa = *reinterpret_cast<const ulonglong2*>(W + k * WID + c0);
        ulonglong2 wb = *reinterpret_cast<const ulonglong2*>(W + k * WID + c0 + 4);
        acc[0][0] = ffma2(x0, wa.x, acc[0][0]); acc[0][1] = ffma2(x0, wa.y, acc[0][1]);
        acc[0][2] = ffma2(x0, wb.x, acc[0][2]); acc[0][3] = ffma2(x0, wb.y, acc[0][3]);
        acc[1][0] = ffma2(x1, wa.x, acc[1][0]); acc[1][1] = ffma2(x1, wa.y, acc[1][1]);
        acc[1][2] = ffma2(x1, wb.x, acc[1][2]); acc[1][3] = ffma2(x1, wb.y, acc[1][3]);
        acc[2][0] = ffma2(x2, wa.x, acc[2][0]); acc[2][1] = ffma2(x2, wa.y, acc[2][1]);
        acc[2][2] = ffma2(x2, wb.x, acc[2][2]); acc[2][3] = ffma2(x2, wb.y, acc[2][3]);
        acc[3][0] = ffma2(x3, wa.x, acc[3][0]); acc[3][1] = ffma2(x3, wa.y, acc[3][1]);
        acc[3][2] = ffma2(x3, wb.x, acc[3][2]); acc[3][3] = ffma2(x3, wb.y, acc[3][3]);
    }
}

__device__ __forceinline__ void storeT(float* __restrict__ Ht,
                                       const float* __restrict__ bias,
                                       int c0, int r0, ull acc[4][4]) {
#pragma unroll
    for (int j = 0; j < 4; j++) {
        int c = c0 + 2 * j;
        float bl = bias[c], bh = bias[c + 1];
        float lo0, hi0, lo1, hi1, lo2, hi2, lo3, hi3;
        unpack2(acc[0][j], lo0, hi0);
        unpack2(acc[1][j], lo1, hi1);
        unpack2(acc[2][j], lo2, hi2);
        unpack2(acc[3][j], lo3, hi3);
        float4 v;
        v.x = fmaxf(lo0 + bl, 0.f); v.y = fmaxf(lo1 + bl, 0.f);
        v.z = fmaxf(lo2 + bl, 0.f); v.w = fmaxf(lo3 + bl, 0.f);
        *reinterpret_cast<float4*>(Ht + c * HSTR + r0) = v;
        v.x = fmaxf(hi0 + bh, 0.f); v.y = fmaxf(hi1 + bh, 0.f);
        v.z = fmaxf(hi2 + bh, 0.f); v.w = fmaxf(hi3 + bh, 0.f);
        *reinterpret_cast<float4*>(Ht + (c + 1) * HSTR + r0) = v;
    }
}

__global__ void __launch_bounds__(ENC_T, 1)
k_encoder(const float* __restrict__ X, const int* __restrict__ seg,
          const float* __restrict__ W1, const float* __restrict__ b1,
          const float* __restrict__ W2, const float* __restrict__ b2,
          const float* __restrict__ W3, const float* __restrict__ b3,
          int N, int numTiles) {
    extern __shared__ float sm[];
    float* sV  = sm;
    float* sW1 = sm + 160;
    float* sB1 = sm + 5280;
    float* sB2 = sm + 5408;
    float* sB3 = sm + 5536;
    float* sW2 = sm + 5664;
    float* sW3 = sm + 22048;
    float* sH  = sm + 38432;
    int*   sSeg = (int*)(sm + 55328);

    int tid = threadIdx.x;
    int wid = tid >> 5;
    int lane = tid & 31;
    int c0 = wid * 8;       // this warp's 8 columns
    int r0 = lane * 4;      // this lane's 4 rows

    for (int i = tid; i < D_IN * NHEADS; i += ENC_T) sV[i] = g_V[i];
    for (int i = tid; i < 5120; i += ENC_T) sW1[i] = W1[i];
    for (int i = tid; i < 128; i += ENC_T) { sB1[i] = b1[i]; sB2[i] = b2[i]; sB3[i] = b3[i]; }
    for (int i = tid; i < 16384; i += ENC_T) { sW2[i] = W2[i]; sW3[i] = W3[i]; }

    ull acc[4][4];

    for (int tile = blockIdx.x; tile < numTiles; tile += gridDim.x) {
        int row0 = tile * TILE;
        int valid = N - row0; if (valid > TILE) valid = TILE;

        __syncthreads();  // previous tile fully consumed

        // stage X transposed: sH[d*HSTR + r] = X[(row0+r)*40 + d]
        for (int i = tid; i < TILE * D_IN; i += ENC_T) {
            int r = i / D_IN, d = i - r * D_IN;
            int g = row0 + r;
            sH[d * HSTR + r] = (g < N) ? X[g * D_IN + d] : 0.f;
        }
        if (tid < TILE) sSeg[tid] = (row0 + tid < N) ? seg[row0 + tid] : -1;
        __syncthreads();

        // per-row partial logit from X while staged (thread -> (row, head))
        {
            int r = tid >> 2, h = tid & 3;
            float p = 0.f;
#pragma unroll
            for (int d = 0; d < D_IN; d++) p += sH[d * HSTR + r] * sV[d * 4 + h];
            int n = row0 + r;
            if (n < N) g_P[n * 4 + h] = p;
        }

        // layer 1: Xt -> acc -> Ht
        layerT<D_IN>(sH, sW1, c0, r0, acc);
        __syncthreads();
        storeT(sH, sB1, c0, r0, acc);
        __syncthreads();
        // layer 2 (in place)
        layerT<WID>(sH, sW2, c0, r0, acc);
        __syncthreads();
        storeT(sH, sB2, c0, r0, acc);
        __syncthreads();
        // layer 3 (in place)
        layerT<WID>(sH, sW3, c0, r0, acc);
        __syncthreads();
        storeT(sH, sB3, c0, r0, acc);
        __syncthreads();

        // sorted-segment accumulation: thread -> (column, quarter-chunk of rows)
        {
            int c = tid & 127, q = tid >> 7;
            int rs = q * 32;
            int re = rs + 32; if (re > valid) re = valid;
            if (rs < valid) {
                float a = 0.f; int cur = sSeg[rs];
                const float* col = sH + c * HSTR;
                for (int r = rs; r < re; r++) {
                    int s = sSeg[r];
                    if (s != cur) { atomicAdd(&g_segSum[cur * WID + c], a); a = 0.f; cur = s; }
                    a += col[r];
                }
                atomicAdd(&g_segSum[cur * WID + c], a);
                if (c == 0) {  // counts (4 threads)
                    float ca = 0.f; int cc = sSeg[rs];
                    for (int r = rs; r < re; r++) {
                        int s = sSeg[r];
                        if (s != cc) { atomicAdd(&g_segCnt[cc], ca); ca = 0.f; cc = s; }
                        ca += 1.f;
                    }
                    atomicAdd(&g_segCnt[cc], ca);
                }
            }
        }
    }
}

// ---------------------------------------------------------------------------
// K3: rho. 128 blocks x 16 segments; Wr staged in smem once per block.
// Thread c computes agg[s][c] for all 16 segments (weight reuse in regs).
// ---------------------------------------------------------------------------
#define RHO_SEGS 16
__global__ void __launch_bounds__(WID, 1)
k_rho(const float* __restrict__ Wr, const float* __restrict__ br) {
    extern __shared__ float sWr[];                 // 16384 floats
    __shared__ float sMean[RHO_SEGS][WID];
    __shared__ float sAgg[RHO_SEGS][WID];

    int c = threadIdx.x;
    int s0 = blockIdx.x * RHO_SEGS;

    for (int i = c; i < WID * WID; i += WID) sWr[i] = Wr[i];
    for (int i = 0; i < RHO_SEGS; i++) {
        float cnt = g_segCnt[s0 + i];
        float inv = 1.f / fmaxf(cnt, 1.f);
        sMean[i][c] = g_segSum[(s0 + i) * WID + c] * inv;
    }
    __syncthreads();

    float a[RHO_SEGS];
#pragma unroll
    for (int i = 0; i < RHO_SEGS; i++) a[i] = br[c];
#pragma unroll 4
    for (int k = 0; k < WID; k++) {
        float w = sWr[k * WID + c];
#pragma unroll
        for (int i = 0; i < RHO_SEGS; i++) a[i] += sMean[i][k] * w;
    }
#pragma unroll
    for (int i = 0; i < RHO_SEGS; i++) sAgg[i][c] = fmaxf(a[i], 0.f);
    __syncthreads();

    // t[s][h] = sum_c sAgg[s][c] * V[40+c][h] ; 64 (s,h) pairs, 2 threads each
    if (c < RHO_SEGS * NHEADS * 2) {
        int pair = c >> 1, half = c & 1;
        int si = pair >> 2, h = pair & 3;
        float t = 0.f;
#pragma unroll 8
        for (int k = half * 64; k < half * 64 + 64; k++)
            t += sAgg[si][k] * g_V[(D_IN + k) * 4 + h];
        atomicAdd(&g_t[(s0 + si) * 4 + h], t);   // g_t zeroed below via init kernel
    }
}

// zero g_t before k_rho (it accumulates via atomics)
__global__ void k_zero_t() {
    int i = blockIdx.x * blockDim.x + threadIdx.x;
    if (i < NSEG * NHEADS) g_t[i] = 0.f;
}

// ---------------------------------------------------------------------------
// K4: finish logits: e = exp((p_x + t_seg)/8); denominators via warp-agg atomics
// ---------------------------------------------------------------------------
__global__ void k_attn(const int* __restrict__ seg, int N) {
    int n = blockIdx.x * 256 + threadIdx.x;
    bool ok = (n < N);
    int sg = ok ? seg[n] : -1;
    int sgl = (sg >= 0) ? sg : 0;

    float4 p = ok ? *reinterpret_cast<const float4*>(&g_P[n * 4]) : make_float4(0, 0, 0, 0);
    float4 t = *reinterpret_cast<const float4*>(&g_t[sgl * 4]);
    const float sc = 0.125f;
    float e0 = ok ? __expf((p.x + t.x) * sc) : 0.f;
    float e1 = ok ? __expf((p.y + t.y) * sc) : 0.f;
    float e2 = ok ? __expf((p.z + t.z) * sc) : 0.f;
    float e3 = ok ? __expf((p.w + t.w) * sc) : 0.f;

    if (ok) *reinterpret_cast<float4*>(&g_P[n * 4]) = make_float4(e0, e1, e2, e3);

    unsigned full = 0xffffffffu;
    int lane = threadIdx.x & 31;
    int sg0 = __shfl_sync(full, sg, 0);
    bool uni = __all_sync(full, sg == sg0);
    if (uni) {
        float r0 = e0, r1 = e1, r2 = e2, r3 = e3;
#pragma unroll
        for (int off = 16; off > 0; off >>= 1) {
            r0 += __shfl_down_sync(full, r0, off);
            r1 += __shfl_down_sync(full, r1, off);
            r2 += __shfl_down_sync(full, r2, off);
            r3 += __shfl_down_sync(full, r3, off);
        }
        if (lane == 0 && sg0 >= 0) {
            atomicAdd(&g_den[sg0 * 4 + 0], r0); atomicAdd(&g_den[sg0 * 4 + 1], r1);
            atomicAdd(&g_den[sg0 * 4 + 2], r2); atomicAdd(&g_den[sg0 * 4 + 3], r3);
        }
    } else if (sg >= 0) {
        atomicAdd(&g_den[sg * 4 + 0], e0); atomicAdd(&g_den[sg * 4 + 1], e1);
        atomicAdd(&g_den[sg * 4 + 2], e2); atomicAdd(&g_den[sg * 4 + 3], e3);
    }
}

// ---------------------------------------------------------------------------
// K5: normalize, output [HEADS, N, 1]
// ---------------------------------------------------------------------------
__global__ void k_norm(const int* __restrict__ seg, float* __restrict__ out, int N) {
    int n = blockIdx.x * 256 + threadIdx.x;
    if (n >= N) return;
    float4 e = *reinterpret_cast<const float4*>(&g_P[n * 4]);
    int s = seg[n];
    float4 d = *reinterpret_cast<const float4*>(&g_den[s * 4]);
    out[0 * N + n] = e.x / d.x;
    out[1 * N + n] = e.y / d.y;
    out[2 * N + n] = e.z / d.z;
    out[3 * N + n] = e.w / d.w;
}

// ---------------------------------------------------------------------------
extern "C" void kernel_launch(void* const* d_in, const int* in_sizes, int n_in,
                              void* d_out, int out_size) {
    const float* X  = (const float*)d_in[0];
    const int*   sg = (const int*)d_in[1];
    const float* W1 = (const float*)d_in[3];
    const float* b1 = (const float*)d_in[4];
    const float* W2 = (const float*)d_in[5];
    const float* b2 = (const float*)d_in[6];
    const float* W3 = (const float*)d_in[7];
    const float* b3 = (const float*)d_in[8];
    const float* Wr = (const float*)d_in[9];
    const float* br = (const float*)d_in[10];
    const float* Wk = (const float*)d_in[11];
    const float* Wq = (const float*)d_in[12];
    float* out = (float*)d_out;

    int N = in_sizes[0] / D_IN;
    int tiles = (N + TILE - 1) / TILE;

    static int configured = 0;
    cudaFuncSetAttribute(k_encoder, cudaFuncAttributeMaxDynamicSharedMemorySize, ENC_SMEM_BYTES);
    cudaFuncSetAttribute(k_rho, cudaFuncAttributeMaxDynamicSharedMemorySize, WID * WID * 4);
    (void)configured;

    k_zero<<<64, 256>>>();
    k_zero_t<<<(NSEG * NHEADS + 255) / 256, 256>>>();
    k_fold<<<1, (D_IN + WID) * NHEADS>>>(Wk, Wq);
    k_encoder<<<148, ENC_T, ENC_SMEM_BYTES>>>(X, sg, W1, b1, W2, b2, W3, b3, N, tiles);
    k_rho<<<NSEG / RHO_SEGS, WID, WID * WID * 4>>>(Wr, br);
    k_attn<<<(N + 255) / 256, 256>>>(sg, N);
    k_norm<<<(N + 255) / 256, 256>>>(sg, out, N);
}